// round 4
// baseline (speedup 1.0000x reference)
#include <cuda_runtime.h>
#include <math.h>

#define BS 32
#define NA 8400
#define NC 80
#define NB 64
#define TOPK 13
#define CAP 640
#define EPSF 1e-9f
#define IOU_EPS 1e-7f
#define GW 32
#define GH 32
#define BININV 0.05f   // 1/20 px
#define TOUCH_MAX (BS * NB * TOPK)
#define NBLOCKS 296
#define NT 256

// ---------------- scratch (static device globals) ----------------
__device__ int      g_bincnt[GW * GH];
__device__ int      g_bin_start[GW * GH + 1];
__device__ int      g_binoff[GW * GH];
__device__ int      g_abin[NA];
__device__ float    g_bax[NA];
__device__ float    g_bay[NA];
__device__ int      g_baid[NA];
__device__ int      g_cnt     [BS * NA];
__device__ int      g_candj   [BS * NA];
__device__ float    g_met_a   [BS * NA];
__device__ float    g_ov_a    [BS * NA];
__device__ int      g_assigned[BS * NA];
__device__ float    g_norm_al [BS * NA];
__device__ unsigned g_pos_align[BS * NB];   // float bits, >= 0
__device__ unsigned g_pos_over [BS * NB];
__device__ int      g_touch[TOUCH_MAX];
__device__ int      g_ntouch;

// grid barrier state (zero-initialized; gen is monotonically increasing across replays)
__device__ volatile unsigned g_gen;
__device__ unsigned          g_count;

__device__ __forceinline__ void gbar() {
    __threadfence();
    __syncthreads();
    if (threadIdx.x == 0) {
        unsigned gen = g_gen;
        unsigned arrived = atomicAdd(&g_count, 1u);
        if (arrived == NBLOCKS - 1u) {
            g_count = 0u;
            __threadfence();
            g_gen = gen + 1u;
        } else {
            while (g_gen == gen) __nanosleep(32);
        }
        __threadfence();
    }
    __syncthreads();
}

__device__ __forceinline__ float ciou_f(float gx1, float gy1, float gx2, float gy2,
                                        float px1, float py1, float px2, float py2) {
    float w1 = gx2 - gx1, h1 = gy2 - gy1 + IOU_EPS;
    float w2 = px2 - px1, h2 = py2 - py1 + IOU_EPS;
    float iw = fminf(gx2, px2) - fmaxf(gx1, px1);
    float ih = fminf(gy2, py2) - fmaxf(gy1, py1);
    float inter = fmaxf(iw, 0.f) * fmaxf(ih, 0.f);
    float uni = w1 * h1 + w2 * h2 - inter + IOU_EPS;
    float iou = inter / uni;
    float cw = fmaxf(gx2, px2) - fminf(gx1, px1);
    float ch = fmaxf(gy2, py2) - fminf(gy1, py1);
    float c2 = cw * cw + ch * ch + IOU_EPS;
    float dx = px1 + px2 - gx1 - gx2;
    float dy = py1 + py2 - gy1 - gy2;
    float rho2 = (dx * dx + dy * dy) * 0.25f;
    float dat = atanf(w2 / h2) - atanf(w1 / h1);
    float v = 0.4052847345693511f * dat * dat;
    float alpha = v / (v - iou + (1.0f + IOU_EPS));
    return iou - (rho2 / c2 + v * alpha);
}

__device__ __forceinline__ float pow6(float x) { float x2 = x * x; return x2 * x2 * x2; }

// ---------------- the one persistent kernel ----------------
__global__ void __launch_bounds__(NT, 2)
k_fused(const float* __restrict__ pd_scores, const float* __restrict__ pd_bboxes,
        const float* __restrict__ anc, const int* __restrict__ gt_labels,
        const float* __restrict__ gt_bboxes, const float* __restrict__ mask_gt,
        float* __restrict__ out) {
    const int tid = threadIdx.x;
    const int gid = blockIdx.x * NT + tid;
    const int gstride = NBLOCKS * NT;

    __shared__ unsigned long long skey[CAP];
    __shared__ float sov[CAP];
    __shared__ int sb[GW * GH];
    __shared__ int swtot[8];
    __shared__ int sP;
    __shared__ int sfidx[TOPK];
    __shared__ float sfmet[TOPK];
    __shared__ float sfovl[TOPK];
    __shared__ int skfill;
    __shared__ unsigned long long wbest[NT / 32];
    __shared__ int wslot[NT / 32];
    __shared__ int   scol [NT];
    __shared__ float snorm[NT];

    // ---- phase 0: zero scratch ----
    for (int k = gid; k < BS * NA; k += gstride) { g_cnt[k] = 0; g_assigned[k] = -1; }
    for (int k = gid; k < BS * NB; k += gstride) { g_pos_align[k] = 0u; g_pos_over[k] = 0u; }
    for (int k = gid; k < GW * GH; k += gstride) g_bincnt[k] = 0;
    if (gid == 0) g_ntouch = 0;
    gbar();

    // ---- phase 1: bin count ----
    for (int i = gid; i < NA; i += gstride) {
        float ax = anc[i * 2 + 0], ay = anc[i * 2 + 1];
        int bx = min(GW - 1, max(0, (int)(ax * BININV)));
        int by = min(GH - 1, max(0, (int)(ay * BININV)));
        int bin = by * GW + bx;
        g_abin[i] = bin;
        atomicAdd(&g_bincnt[bin], 1);
    }
    gbar();

    // ---- phase 2: scan (block 0 only) ----
    if (blockIdx.x == 0) {
        for (int i = tid; i < GW * GH; i += NT) sb[i] = g_bincnt[i];
        __syncthreads();
        int b0 = sb[tid * 4], b1 = sb[tid * 4 + 1], b2 = sb[tid * 4 + 2], b3 = sb[tid * 4 + 3];
        int t1 = b0 + b1, t2 = t1 + b2, tot = t2 + b3;
        int x = tot;
        int lane = tid & 31, wd = tid >> 5;
        #pragma unroll
        for (int off = 1; off < 32; off <<= 1) {
            int y = __shfl_up_sync(0xFFFFFFFFu, x, off);
            if (lane >= off) x += y;
        }
        if (lane == 31) swtot[wd] = x;
        __syncthreads();
        if (tid == 0) {
            int acc = 0;
            #pragma unroll
            for (int w = 0; w < 8; w++) { int v = swtot[w]; swtot[w] = acc; acc += v; }
        }
        __syncthreads();
        int excl = x - tot + swtot[wd];
        g_bin_start[tid * 4 + 1] = excl + b0;
        g_bin_start[tid * 4 + 2] = excl + t1;
        g_bin_start[tid * 4 + 3] = excl + t2;
        g_bin_start[tid * 4 + 4] = excl + tot;
        g_binoff[tid * 4 + 0] = excl;
        g_binoff[tid * 4 + 1] = excl + b0;
        g_binoff[tid * 4 + 2] = excl + t1;
        g_binoff[tid * 4 + 3] = excl + t2;
        if (tid == 0) g_bin_start[0] = 0;
    }
    gbar();

    // ---- phase 3: scatter anchors into bins ----
    for (int i = gid; i < NA; i += gstride) {
        int bin = g_abin[i];
        int slot = atomicAdd(&g_binoff[bin], 1);
        g_baid[slot] = i;
        g_bax[slot] = anc[i * 2 + 0];
        g_bay[slot] = anc[i * 2 + 1];
    }
    gbar();

    // ---- phase 4: per-row candidates + top-13 + zero-fill + scatter ----
    for (int row = blockIdx.x; row < BS * NB; row += NBLOCKS) {
        __syncthreads();
        if (mask_gt[row] <= 0.f) continue;
        const int b = row >> 6, j = row & 63;
        const int lane = tid & 31, wd = tid >> 5;
        if (tid == 0) sP = 0;
        __syncthreads();

        const float gx1 = gt_bboxes[row * 4 + 0], gy1 = gt_bboxes[row * 4 + 1];
        const float gx2 = gt_bboxes[row * 4 + 2], gy2 = gt_bboxes[row * 4 + 3];
        const int lbl = gt_labels[row];

        int bx_lo = min(GW - 1, max(0, (int)floorf(gx1 * BININV)));
        int bx_hi = min(GW - 1, max(0, (int)floorf(gx2 * BININV)));
        int by_lo = min(GH - 1, max(0, (int)floorf(gy1 * BININV)));
        int by_hi = min(GH - 1, max(0, (int)floorf(gy2 * BININV)));

        for (int by = by_lo; by <= by_hi; by++) {
            int s = g_bin_start[by * GW + bx_lo];
            int e = g_bin_start[by * GW + bx_hi + 1];
            for (int i = s + tid; i < e; i += NT) {
                float ax = g_bax[i], ay = g_bay[i];
                if (!(ax - gx1 > EPSF && ay - gy1 > EPSF && gx2 - ax > EPSF && gy2 - ay > EPSF)) continue;
                int a = g_baid[i];
                long long pos = (long long)b * NA + a;
                const float4 pb = __ldg((const float4*)(pd_bboxes + pos * 4));
                float ov = fmaxf(ciou_f(gx1, gy1, gx2, gy2, pb.x, pb.y, pb.z, pb.w), 0.f);
                float met = __ldg(pd_scores + pos * NC + lbl) * pow6(ov);
                if (met > 0.f) {
                    int slot = atomicAdd(&sP, 1);
                    if (slot < CAP) {
                        skey[slot] = ((unsigned long long)__float_as_uint(met) << 32)
                                   | (unsigned)(0xFFFFFFFFu - (unsigned)a);
                        sov[slot] = ov;
                    }
                }
            }
        }
        __syncthreads();
        int P = min(sP, CAP);
        int nsel = min(P, TOPK);

        for (int r = 0; r < nsel; r++) {
            unsigned long long best = 0; int bslot = -1;
            for (int i = tid; i < P; i += NT)
                if (skey[i] > best) { best = skey[i]; bslot = i; }
            #pragma unroll
            for (int off = 16; off > 0; off >>= 1) {
                unsigned long long ob = __shfl_down_sync(0xFFFFFFFFu, best, off);
                int os = __shfl_down_sync(0xFFFFFFFFu, bslot, off);
                if (ob > best) { best = ob; bslot = os; }
            }
            if (lane == 0) { wbest[wd] = best; wslot[wd] = bslot; }
            __syncthreads();
            if (tid == 0) {
                unsigned long long bb = wbest[0]; int bs2 = wslot[0];
                #pragma unroll
                for (int w = 1; w < NT / 32; w++)
                    if (wbest[w] > bb) { bb = wbest[w]; bs2 = wslot[w]; }
                sfidx[r] = (int)(0xFFFFFFFFu - (unsigned)(bb & 0xFFFFFFFFull));
                sfmet[r] = __uint_as_float((unsigned)(bb >> 32));
                sfovl[r] = sov[bs2];
                skey[bs2] = 0ull;
            }
            __syncthreads();
        }

        if (tid == 0) {
            int kfill = nsel;
            if (nsel < TOPK) {
                // top_k fills remaining slots with smallest-index zero-metric anchors;
                // they survive only if inside the gt box.
                int slots = nsel;
                int a = 0;
                while (slots < TOPK && a < NA) {
                    bool ispos = false;
                    for (int t = 0; t < nsel; t++)
                        if (sfidx[t] == a) { ispos = true; break; }
                    if (!ispos) {
                        slots++;
                        float ax = anc[a * 2 + 0], ay = anc[a * 2 + 1];
                        if (ax - gx1 > EPSF && ay - gy1 > EPSF && gx2 - ax > EPSF && gy2 - ay > EPSF) {
                            sfidx[kfill] = a; sfmet[kfill] = 0.f; sfovl[kfill] = 0.f;
                            kfill++;
                        }
                    }
                    a++;
                }
            }
            skfill = kfill;
        }
        __syncthreads();

        if (tid < skfill) {
            int a = sfidx[tid];
            int pos = b * NA + a;
            int old = atomicAdd(&g_cnt[pos], 1);
            if (old == 0) {
                int t = atomicAdd(&g_ntouch, 1);
                g_touch[t] = pos;
            }
            g_candj[pos] = j;        // race only matters when cnt>1 (value unused then)
            g_met_a[pos] = sfmet[tid];
            g_ov_a[pos]  = sfovl[tid];
        }
    }
    gbar();

    // ---- phase 5: compact per-anchor resolution + pos maxima ----
    {
        int ntouch = g_ntouch;
        for (int i = gid; i < ntouch; i += gstride) {
            int pos = g_touch[i];
            int b = pos / NA;
            int a = pos - b * NA;
            int c = g_cnt[pos];
            int jm; float met, ov;
            if (c == 1) {
                jm = g_candj[pos]; met = g_met_a[pos]; ov = g_ov_a[pos];
            } else {
                float ax = __ldg(anc + a * 2 + 0), ay = __ldg(anc + a * 2 + 1);
                const float4 pb = __ldg((const float4*)(pd_bboxes + (long long)pos * 4));
                float bestov = -1.f; int bestj = 0;
                for (int j = 0; j < NB; j++) {
                    float ovj = 0.f;
                    if (__ldg(mask_gt + b * NB + j) > 0.f) {
                        const float4 g = __ldg((const float4*)(gt_bboxes + (b * NB + j) * 4));
                        if (ax - g.x > EPSF && ay - g.y > EPSF && g.z - ax > EPSF && g.w - ay > EPSF)
                            ovj = fmaxf(ciou_f(g.x, g.y, g.z, g.w, pb.x, pb.y, pb.z, pb.w), 0.f);
                    }
                    if (ovj > bestov) { bestov = ovj; bestj = j; }
                }
                jm = bestj; ov = bestov;
                met = (ov > 0.f)
                    ? __ldg(pd_scores + (long long)pos * NC + __ldg(gt_labels + b * NB + jm)) * pow6(ov)
                    : 0.f;
            }
            g_assigned[pos] = jm;
            g_norm_al[pos]  = met;
            atomicMax(&g_pos_align[b * NB + jm], __float_as_uint(met));
            atomicMax(&g_pos_over [b * NB + jm], __float_as_uint(ov));
        }
    }
    gbar();

    // ---- phase 6: write all outputs ----
    {
        const long long L = (long long)BS * NA;
        const int TILES_PER_B = (NA + NT - 1) / NT;   // 33
        for (int t = blockIdx.x; t < BS * TILES_PER_B; t += NBLOCKS) {
            int b = t / TILES_PER_B;
            int base = (t - b * TILES_PER_B) * NT;
            int nA = min(NT, NA - base);
            __syncthreads();
            if (tid < nA) {
                int a = base + tid;
                long long pos = (long long)b * NA + a;
                int jm = g_assigned[pos];
                bool fg = (jm >= 0);
                int j0 = fg ? jm : 0;
                int label = gt_labels[b * NB + j0];
                const float4 gb = *(const float4*)(gt_bboxes + (b * NB + j0) * 4);
                out[pos] = (float)label;
                *(float4*)(out + L + pos * 4) = gb;
                out[L * 5 + L * NC + pos] = fg ? 1.f : 0.f;
                out[L * 6 + L * NC + pos] = (float)j0;
                float norm = 0.f;
                if (fg) {
                    float pa = __uint_as_float(g_pos_align[b * NB + jm]);
                    float po = __uint_as_float(g_pos_over [b * NB + jm]);
                    norm = g_norm_al[pos] * po / (pa + EPSF);
                }
                scol [tid] = fg ? label : -1;
                snorm[tid] = norm;
            }
            __syncthreads();

            float4* srow = (float4*)(out + L * 5 + ((long long)b * NA + base) * NC);
            int total = nA * (NC / 4);
            for (int k = tid; k < total; k += NT) {
                int la = k / (NC / 4), q = k - la * (NC / 4);
                float4 v = make_float4(0.f, 0.f, 0.f, 0.f);
                int col = scol[la];
                if ((col >> 2) == q) {
                    float n = snorm[la];
                    int r = col & 3;
                    if (r == 0) v.x = n; else if (r == 1) v.y = n; else if (r == 2) v.z = n; else v.w = n;
                }
                srow[k] = v;
            }
        }
    }
}

// ---------------- launch ----------------
extern "C" void kernel_launch(void* const* d_in, const int* in_sizes, int n_in,
                              void* d_out, int out_size) {
    const float* pd_scores = (const float*)d_in[0];
    const float* pd_bboxes = (const float*)d_in[1];
    const float* anc       = (const float*)d_in[2];
    const int*   gt_labels = (const int*)  d_in[3];
    const float* gt_bboxes = (const float*)d_in[4];
    const float* mask_gt   = (const float*)d_in[5];
    float* out = (float*)d_out;

    k_fused<<<NBLOCKS, NT>>>(pd_scores, pd_bboxes, anc, gt_labels, gt_bboxes, mask_gt, out);
}

// round 5
// speedup vs baseline: 1.9548x; 1.9548x over previous
#include <cuda_runtime.h>
#include <math.h>

#define BS 32
#define NA 8400
#define NC 80
#define NB 64
#define TOPK 13
#define CAP 640
#define EPSF 1e-9f
#define IOU_EPS 1e-7f
#define GW 32
#define GH 32
#define BININV 0.05f   // 1/20 px
#define TOUCH_MAX (BS * NB * TOPK)

// ---------------- scratch (static device globals) ----------------
__device__ int      g_bin_start[GW * GH + 1];
__device__ int      g_abin[NA];
__device__ float    g_bax[NA];
__device__ float    g_bay[NA];
__device__ int      g_baid[NA];
__device__ int      g_cnt     [BS * NA];
__device__ int      g_candj   [BS * NA];
__device__ float    g_met_a   [BS * NA];
__device__ float    g_ov_a    [BS * NA];
__device__ int      g_assigned[BS * NA];
__device__ float    g_norm_al [BS * NA];
__device__ unsigned g_pos_align[BS * NB];   // float bits, >= 0
__device__ unsigned g_pos_over [BS * NB];
__device__ int      g_touch[TOUCH_MAX];
__device__ int      g_ntouch;

__device__ __forceinline__ float ciou_f(float gx1, float gy1, float gx2, float gy2,
                                        float px1, float py1, float px2, float py2) {
    float w1 = gx2 - gx1, h1 = gy2 - gy1 + IOU_EPS;
    float w2 = px2 - px1, h2 = py2 - py1 + IOU_EPS;
    float iw = fminf(gx2, px2) - fmaxf(gx1, px1);
    float ih = fminf(gy2, py2) - fmaxf(gy1, py1);
    float inter = fmaxf(iw, 0.f) * fmaxf(ih, 0.f);
    float uni = w1 * h1 + w2 * h2 - inter + IOU_EPS;
    float iou = inter / uni;
    float cw = fmaxf(gx2, px2) - fminf(gx1, px1);
    float ch = fmaxf(gy2, py2) - fminf(gy1, py1);
    float c2 = cw * cw + ch * ch + IOU_EPS;
    float dx = px1 + px2 - gx1 - gx2;
    float dy = py1 + py2 - gy1 - gy2;
    float rho2 = (dx * dx + dy * dy) * 0.25f;
    float dat = atanf(w2 / h2) - atanf(w1 / h1);
    float v = 0.4052847345693511f * dat * dat;
    float alpha = v / (v - iou + (1.0f + IOU_EPS));
    return iou - (rho2 / c2 + v * alpha);
}

__device__ __forceinline__ float pow6(float x) { float x2 = x * x; return x2 * x2 * x2; }

// ---------------- kernel P: fused zero + binning ----------------
// block 0 (1024 thr): full bin count -> scan -> scatter in shared memory.
// blocks 1..: zero the per-anchor scratch concurrently.
__global__ void k_prep(const float* __restrict__ anc) {
    int tid = threadIdx.x;
    if (blockIdx.x == 0) {
        __shared__ int scnt[GW * GH];
        __shared__ int soff[GW * GH];
        scnt[tid] = 0;
        __syncthreads();
        for (int i = tid; i < NA; i += 1024) {
            float ax = anc[i * 2 + 0], ay = anc[i * 2 + 1];
            int bx = min(GW - 1, max(0, (int)(ax * BININV)));
            int by = min(GH - 1, max(0, (int)(ay * BININV)));
            int bin = by * GW + bx;
            g_abin[i] = bin;
            atomicAdd(&scnt[bin], 1);
        }
        __syncthreads();
        int myc = scnt[tid];
        for (int off = 1; off < GW * GH; off <<= 1) {
            int v = (tid >= off) ? scnt[tid - off] : 0;
            __syncthreads();
            scnt[tid] += v;
            __syncthreads();
        }
        g_bin_start[tid + 1] = scnt[tid];
        if (tid == 0) { g_bin_start[0] = 0; g_ntouch = 0; }
        soff[tid] = scnt[tid] - myc;   // exclusive
        __syncthreads();
        for (int i = tid; i < NA; i += 1024) {
            int bin = g_abin[i];
            int slot = atomicAdd(&soff[bin], 1);
            g_baid[slot] = i;
            g_bax[slot] = anc[i * 2 + 0];
            g_bay[slot] = anc[i * 2 + 1];
        }
    } else {
        int gid = (blockIdx.x - 1) * 1024 + tid;
        int stride = (gridDim.x - 1) * 1024;
        for (int k = gid; k < BS * NA; k += stride) { g_cnt[k] = 0; g_assigned[k] = -1; }
        for (int k = gid; k < BS * NB; k += stride) { g_pos_align[k] = 0u; g_pos_over[k] = 0u; }
    }
}

// ---------------- kernel B: per-row candidates + top-13 + zero-fill + scatter ----------------
__global__ void k_rows(const float* __restrict__ pd_scores, const float* __restrict__ pd_bboxes,
                       const float* __restrict__ anc, const int* __restrict__ gt_labels,
                       const float* __restrict__ gt_bboxes, const float* __restrict__ mask_gt) {
    const int row = blockIdx.x;            // b*NB + j
    const int b = row >> 6, j = row & 63;
    const int tid = threadIdx.x;
    const int lane = tid & 31, wid = tid >> 5;

    __shared__ unsigned long long skey[CAP];
    __shared__ float sov[CAP];
    __shared__ int sP;
    __shared__ int sfidx[TOPK];
    __shared__ float sfmet[TOPK];
    __shared__ float sfovl[TOPK];
    __shared__ int skfill;
    __shared__ unsigned long long wbest[2];
    __shared__ int wslot[2];

    if (mask_gt[row] <= 0.f) return;

    if (tid == 0) sP = 0;
    __syncthreads();

    const float gx1 = gt_bboxes[row * 4 + 0], gy1 = gt_bboxes[row * 4 + 1];
    const float gx2 = gt_bboxes[row * 4 + 2], gy2 = gt_bboxes[row * 4 + 3];
    const int lbl = gt_labels[row];

    int bx_lo = min(GW - 1, max(0, (int)floorf(gx1 * BININV)));
    int bx_hi = min(GW - 1, max(0, (int)floorf(gx2 * BININV)));
    int by_lo = min(GH - 1, max(0, (int)floorf(gy1 * BININV)));
    int by_hi = min(GH - 1, max(0, (int)floorf(gy2 * BININV)));

    for (int by = by_lo; by <= by_hi; by++) {
        int s = g_bin_start[by * GW + bx_lo];
        int e = g_bin_start[by * GW + bx_hi + 1];
        for (int i = s + tid; i < e; i += 64) {
            float ax = g_bax[i], ay = g_bay[i];
            if (!(ax - gx1 > EPSF && ay - gy1 > EPSF && gx2 - ax > EPSF && gy2 - ay > EPSF)) continue;
            int a = g_baid[i];
            long long pos = (long long)b * NA + a;
            const float4 pb = __ldg((const float4*)(pd_bboxes + pos * 4));
            float ov = fmaxf(ciou_f(gx1, gy1, gx2, gy2, pb.x, pb.y, pb.z, pb.w), 0.f);
            float met = __ldg(pd_scores + pos * NC + lbl) * pow6(ov);
            if (met > 0.f) {
                int slot = atomicAdd(&sP, 1);
                if (slot < CAP) {
                    skey[slot] = ((unsigned long long)__float_as_uint(met) << 32)
                               | (unsigned)(0xFFFFFFFFu - (unsigned)a);
                    sov[slot] = ov;
                }
            }
        }
    }
    __syncthreads();
    int P = min(sP, CAP);
    int nsel = min(P, TOPK);

    for (int r = 0; r < nsel; r++) {
        unsigned long long best = 0; int bslot = -1;
        for (int i = tid; i < P; i += 64)
            if (skey[i] > best) { best = skey[i]; bslot = i; }
        #pragma unroll
        for (int off = 16; off > 0; off >>= 1) {
            unsigned long long ob = __shfl_down_sync(0xFFFFFFFFu, best, off);
            int os = __shfl_down_sync(0xFFFFFFFFu, bslot, off);
            if (ob > best) { best = ob; bslot = os; }
        }
        if (lane == 0) { wbest[wid] = best; wslot[wid] = bslot; }
        __syncthreads();
        if (tid == 0) {
            unsigned long long bb = wbest[0]; int bs2 = wslot[0];
            if (wbest[1] > bb) { bb = wbest[1]; bs2 = wslot[1]; }
            sfidx[r] = (int)(0xFFFFFFFFu - (unsigned)(bb & 0xFFFFFFFFull));
            sfmet[r] = __uint_as_float((unsigned)(bb >> 32));
            sfovl[r] = sov[bs2];
            skey[bs2] = 0ull;
        }
        __syncthreads();
    }

    if (tid == 0) {
        int kfill = nsel;
        if (nsel < TOPK) {
            // top_k fills remaining slots with smallest-index zero-metric anchors;
            // they survive only if inside the gt box. (loop runs <= ~26 iters)
            int slots = nsel;
            int a = 0;
            while (slots < TOPK && a < NA) {
                bool ispos = false;
                for (int t = 0; t < nsel; t++)
                    if (sfidx[t] == a) { ispos = true; break; }
                if (!ispos) {
                    slots++;
                    float ax = anc[a * 2 + 0], ay = anc[a * 2 + 1];
                    if (ax - gx1 > EPSF && ay - gy1 > EPSF && gx2 - ax > EPSF && gy2 - ay > EPSF) {
                        sfidx[kfill] = a; sfmet[kfill] = 0.f; sfovl[kfill] = 0.f;
                        kfill++;
                    }
                }
                a++;
            }
        }
        skfill = kfill;
    }
    __syncthreads();

    if (tid < skfill) {
        int a = sfidx[tid];
        int pos = b * NA + a;
        int old = atomicAdd(&g_cnt[pos], 1);
        if (old == 0) {
            int t = atomicAdd(&g_ntouch, 1);
            g_touch[t] = pos;
        }
        g_candj[pos] = j;            // race only matters when cnt>1 (value unused then)
        g_met_a[pos] = sfmet[tid];
        g_ov_a[pos]  = sfovl[tid];
    }
}

// ---------------- kernel C: compact per-anchor resolution + pos maxima ----------------
__global__ void k_resolve(const float* __restrict__ pd_scores, const float* __restrict__ pd_bboxes,
                          const float* __restrict__ anc, const int* __restrict__ gt_labels,
                          const float* __restrict__ gt_bboxes, const float* __restrict__ mask_gt) {
    int i = blockIdx.x * blockDim.x + threadIdx.x;
    if (i >= g_ntouch) return;
    int pos = g_touch[i];
    int b = pos / NA;
    int a = pos - b * NA;
    int c = g_cnt[pos];
    int jm; float met, ov;
    if (c == 1) {
        jm = g_candj[pos]; met = g_met_a[pos]; ov = g_ov_a[pos];
    } else {
        // multi-gt anchor: argmax_j overlaps (first max wins), over ALL gts
        float ax = __ldg(anc + a * 2 + 0), ay = __ldg(anc + a * 2 + 1);
        const float4 pb = __ldg((const float4*)(pd_bboxes + (long long)pos * 4));
        float bestov = -1.f; int bestj = 0;
        for (int j = 0; j < NB; j++) {
            float ovj = 0.f;
            if (__ldg(mask_gt + b * NB + j) > 0.f) {
                const float4 g = __ldg((const float4*)(gt_bboxes + (b * NB + j) * 4));
                if (ax - g.x > EPSF && ay - g.y > EPSF && g.z - ax > EPSF && g.w - ay > EPSF)
                    ovj = fmaxf(ciou_f(g.x, g.y, g.z, g.w, pb.x, pb.y, pb.z, pb.w), 0.f);
            }
            if (ovj > bestov) { bestov = ovj; bestj = j; }
        }
        jm = bestj; ov = bestov;
        met = (ov > 0.f)
            ? __ldg(pd_scores + (long long)pos * NC + __ldg(gt_labels + b * NB + jm)) * pow6(ov)
            : 0.f;
    }
    g_assigned[pos] = jm;
    g_norm_al[pos]  = met;
    atomicMax(&g_pos_align[b * NB + jm], __float_as_uint(met));
    atomicMax(&g_pos_over [b * NB + jm], __float_as_uint(ov));
}

// ---------------- kernel D: write all outputs (float4 score rows) ----------------
#define D_ANCH 128
__global__ void k_out(const int* __restrict__ gt_labels, const float* __restrict__ gt_bboxes,
                      float* __restrict__ out) {
    int b = blockIdx.y;
    int base = blockIdx.x * D_ANCH;
    int tid = threadIdx.x;
    __shared__ int   scol [D_ANCH];   // score column (-1 if background)
    __shared__ float snorm[D_ANCH];
    const long long L = (long long)BS * NA;
    int nA = min(D_ANCH, NA - base);

    if (tid < nA) {
        int a = base + tid;
        long long pos = (long long)b * NA + a;
        int jm = g_assigned[pos];
        bool fg = (jm >= 0);
        int j0 = fg ? jm : 0;
        int label = gt_labels[b * NB + j0];
        const float4 gb = *(const float4*)(gt_bboxes + (b * NB + j0) * 4);
        out[pos] = (float)label;
        *(float4*)(out + L + pos * 4) = gb;
        out[L * 5 + L * NC + pos] = fg ? 1.f : 0.f;
        out[L * 6 + L * NC + pos] = (float)j0;
        float norm = 0.f;
        if (fg) {
            float pa = __uint_as_float(g_pos_align[b * NB + jm]);
            float po = __uint_as_float(g_pos_over [b * NB + jm]);
            norm = g_norm_al[pos] * po / (pa + EPSF);
        }
        scol [tid] = fg ? label : -1;
        snorm[tid] = norm;
    }
    __syncthreads();

    // score rows: NC=80 floats = 20 float4 per anchor
    float4* srow = (float4*)(out + L * 5 + ((long long)b * NA + base) * NC);
    int total = nA * (NC / 4);
    for (int k = tid; k < total; k += blockDim.x) {
        int la = k / (NC / 4), q = k - la * (NC / 4);
        float4 v = make_float4(0.f, 0.f, 0.f, 0.f);
        int col = scol[la];
        if ((col >> 2) == q) {
            float n = snorm[la];
            int r = col & 3;
            if (r == 0) v.x = n; else if (r == 1) v.y = n; else if (r == 2) v.z = n; else v.w = n;
        }
        srow[k] = v;
    }
}

// ---------------- launch ----------------
extern "C" void kernel_launch(void* const* d_in, const int* in_sizes, int n_in,
                              void* d_out, int out_size) {
    const float* pd_scores = (const float*)d_in[0];
    const float* pd_bboxes = (const float*)d_in[1];
    const float* anc       = (const float*)d_in[2];
    const int*   gt_labels = (const int*)  d_in[3];
    const float* gt_bboxes = (const float*)d_in[4];
    const float* mask_gt   = (const float*)d_in[5];
    float* out = (float*)d_out;

    k_prep<<<33, 1024>>>(anc);
    k_rows<<<BS * NB, 64>>>(pd_scores, pd_bboxes, anc, gt_labels, gt_bboxes, mask_gt);
    k_resolve<<<(TOUCH_MAX + 255) / 256, 256>>>(pd_scores, pd_bboxes, anc, gt_labels, gt_bboxes, mask_gt);
    dim3 gridD((NA + D_ANCH - 1) / D_ANCH, BS);
    k_out<<<gridD, 256>>>(gt_labels, gt_bboxes, out);
}